// round 15
// baseline (speedup 1.0000x reference)
#include <cuda_runtime.h>
#include <cuda_fp16.h>
#include <math.h>

// ---------------- problem constants ----------------
#define Bn 8
#define Hn 192
#define Wn 192
#define Cn 64
#define NPIX (Bn*Hn*Wn)          // 294912
#define CV 81
#define CIN0 209
#define P0 216                    // padded channel stride (27 * 8)
#define FLOW_SCALE 271.52900393598527f
#define BN_EPS 1e-3f

// ---------------- scratch (activations in fp16) ----------------
__device__ __half g_bufA[(size_t)NPIX * P0];
__device__ __half g_bufB[(size_t)NPIX * P0];
__device__ float g_dw0pad[9 * P0];
__device__ float g_pw0pad[P0 * 128];

// mish via identity: tanh(softplus(x)) = (s^2+2s)/(s^2+2s+2), s=e^x.
__device__ __forceinline__ float mish(float x) {
    float s = __expf(x);
    float t = s * (s + 2.f);
    float r = x * __fdividef(t, t + 2.f);
    return (x > 15.f) ? x : r;
}

// ---------------- packed f32x2 helpers ----------------
__device__ __forceinline__ unsigned long long pack2(float x, float y) {
    unsigned long long r;
    asm("mov.b64 %0, {%1, %2};" : "=l"(r) : "f"(x), "f"(y));
    return r;
}
__device__ __forceinline__ void unpack2(unsigned long long v, float& x, float& y) {
    asm("mov.b64 {%0, %1}, %2;" : "=f"(x), "=f"(y) : "l"(v));
}
__device__ __forceinline__ void ffma2(unsigned long long& c, unsigned long long a, unsigned long long b) {
    asm("fma.rn.f32x2 %0, %1, %2, %0;" : "+l"(c) : "l"(a), "l"(b));
}

// half4 <-> float helpers
__device__ __forceinline__ void h4_to_f(const uint2 raw, float* f) {
    __half2 h0 = *(const __half2*)&raw.x;
    __half2 h1 = *(const __half2*)&raw.y;
    float2 a = __half22float2(h0), b = __half22float2(h1);
    f[0] = a.x; f[1] = a.y; f[2] = b.x; f[3] = b.y;
}
__device__ __forceinline__ uint2 f_to_h4(float a, float b, float c, float d) {
    __half2 h0 = __floats2half2_rn(a, b);
    __half2 h1 = __floats2half2_rn(c, d);
    uint2 r;
    r.x = *(const unsigned*)&h0;
    r.y = *(const unsigned*)&h1;
    return r;
}

// ---------------- kernel 0: pad dw0 + pw0 weights ----------------
__global__ void pad_w_kernel(const float* __restrict__ dw0, const float* __restrict__ pw0)
{
    int idx = blockIdx.x * blockDim.x + threadIdx.x;
    if (idx < 9 * P0) {
        int c = idx % P0;
        int k = idx / P0;
        g_dw0pad[idx] = (c < CIN0) ? dw0[k * CIN0 + c] : 0.f;
    }
    if (idx < P0 * 128) {
        int n = idx % 128;
        int k = idx / 128;
        g_pw0pad[idx] = (k < CIN0) ? pw0[k * 128 + n] : 0.f;
    }
}

// ---------------- kernel 1: cost volume (+ concat fold in DXB==0 pass) ----------------
template<int DXB, int NDX>
__global__ __launch_bounds__(128)
void cost_kernel(const float* __restrict__ prv, const float* __restrict__ nxt,
                 __half* __restrict__ x0)
{
    __shared__ float sbuf[16 * 661];
    __shared__ float sout[NDX * 9 * 257];

    const int tid  = threadIdx.x;
    const int lane = tid & 31;
    const int wp   = tid >> 5;
    const int bx = blockIdx.x, by = blockIdx.y, b = blockIdx.z;

    const int x    = bx * 32 + lane;
    const int y0   = by * 8 + wp * 2;
    const size_t pix0 = (size_t)(b * Hn + y0) * Wn + x;
    const size_t pix1 = pix0 + Wn;

    float acc0[NDX * 9], acc1[NDX * 9];
#pragma unroll
    for (int t = 0; t < NDX * 9; t++) { acc0[t] = 0.f; acc1[t] = 0.f; }

#pragma unroll 1
    for (int chp = 0; chp < 4; chp++) {
        __syncthreads();
#pragma unroll 4
        for (int k = 0; k < 80; k++) {
            int i = tid + k * 128;
            int c = i & 15;
            int rest = i >> 4;
            int xs = rest % 40;
            int r  = rest / 40;
            int gy = by * 8 + r - 4;
            int gx = bx * 32 + xs - 4;
            float v = 0.f;
            if (gy >= 0 && gy < Hn && gx >= 0 && gx < Wn)
                v = nxt[((size_t)(b * Hn + gy) * Wn + gx) * Cn + chp * 16 + c];
            sbuf[c * 661 + r * 41 + xs] = v;
        }
        __syncthreads();

#pragma unroll 1
        for (int c4 = 0; c4 < 4; c4++) {
            float4 pa = *(const float4*)(prv + pix0 * Cn + chp * 16 + c4 * 4);
            float4 pb = *(const float4*)(prv + pix1 * Cn + chp * 16 + c4 * 4);
            float pav[4] = {pa.x, pa.y, pa.z, pa.w};
            float pbv[4] = {pb.x, pb.y, pb.z, pb.w};
#pragma unroll
            for (int cc = 0; cc < 4; cc++) {
                const float* splane = &sbuf[(c4 * 4 + cc) * 661];
#pragma unroll
                for (int rr = 0; rr < 10; rr++) {
                    const float* q = &splane[(wp * 2 + rr) * 41 + lane + DXB];
#pragma unroll
                    for (int d = 0; d < NDX; d++) {
                        float qv = q[d];
                        if (rr < 9)  acc0[rr * NDX + d]       = fmaf(pav[cc], qv, acc0[rr * NDX + d]);
                        if (rr >= 1) acc1[(rr - 1) * NDX + d] = fmaf(pbv[cc], qv, acc1[(rr - 1) * NDX + d]);
                    }
                }
            }
        }
    }

    __syncthreads();
    const int pl0 = wp * 64 + lane;
#pragma unroll
    for (int t = 0; t < NDX * 9; t++) {
        float v0 = acc0[t] * (1.f / 64.f); v0 = (v0 > 0.f) ? v0 : 0.1f * v0;
        float v1 = acc1[t] * (1.f / 64.f); v1 = (v1 > 0.f) ? v1 : 0.1f * v1;
        sout[t * 257 + pl0]      = v0;
        sout[t * 257 + pl0 + 32] = v1;
    }
    __syncthreads();

    const int TOT = 256 * NDX * 9;
    for (int i = tid; i < TOT; i += 128) {
        int px = i / (NDX * 9);
        int t  = i % (NDX * 9);
        int dy = t / NDX, d = t % NDX;
        int yl = px >> 5, xx = px & 31;
        size_t pix = (size_t)(b * Hn + by * 8 + yl) * Wn + bx * 32 + xx;
        x0[pix * P0 + dy * 9 + DXB + d] = __float2half_rn(sout[t * 257 + px]);
    }

    if (DXB == 0) {
        for (int j = tid; j < 256 * 64; j += 128) {
            int px = j >> 6, c = j & 63;
            int yl = px >> 5, xx = px & 31;
            size_t pix = (size_t)(b * Hn + by * 8 + yl) * Wn + bx * 32 + xx;
            x0[pix * P0 + CV + c]      = __float2half_rn(prv[pix * Cn + c]);
            x0[pix * P0 + CV + 64 + c] = __float2half_rn(nxt[pix * Cn + c]);
            if (c >= 57) x0[pix * P0 + 152 + c] = __float2half_rn(0.f);   // 209..215
        }
    }
}

// ---------------- kernel 2: depthwise 3x3, half4 channels, 4 y-outputs/thread ----------------
template<int QUADS, int STRIDE, int WSTRIDE>
__global__ __launch_bounds__(256, 4)
void dw4y_kernel(const __half* __restrict__ X, const float* __restrict__ Wd,
                 __half* __restrict__ Y)
{
    int idx = blockIdx.x * blockDim.x + threadIdx.x;
    if (idx >= (NPIX / 4) * QUADS) return;
    int q    = idx % QUADS;
    int rest = idx / QUADS;
    int w    = rest % Wn;
    int rest2 = rest / Wn;
    int hg   = rest2 % (Hn / 4);
    int b    = rest2 / (Hn / 4);
    const int h0 = hg * 4;

    float4 wv[9];
#pragma unroll
    for (int t = 0; t < 9; t++)
        wv[t] = *(const float4*)(Wd + t * WSTRIDE + q * 4);

    float4 acc[4];
#pragma unroll
    for (int m = 0; m < 4; m++) acc[m] = make_float4(0.f, 0.f, 0.f, 0.f);

    const bool wl = (w - 1 >= 0), wr = (w + 1 < Wn);

#pragma unroll
    for (int r = 0; r < 6; r++) {
        int hh = h0 + r - 1;
        if (hh < 0 || hh >= Hn) continue;
        const __half* rowp = X + ((size_t)((b * Hn + hh) * Wn + w)) * STRIDE + q * 4;
#pragma unroll
        for (int kx = 0; kx < 3; kx++) {
            if (kx == 0 && !wl) continue;
            if (kx == 2 && !wr) continue;
            uint2 raw = *(const uint2*)(rowp + (kx - 1) * STRIDE);
            float xv[4];
            h4_to_f(raw, xv);
#pragma unroll
            for (int m = 0; m < 4; m++) {
                int ky = r - m;
                if (ky < 0 || ky > 2) continue;
                float4 wq = wv[ky * 3 + kx];
                acc[m].x = fmaf(xv[0], wq.x, acc[m].x);
                acc[m].y = fmaf(xv[1], wq.y, acc[m].y);
                acc[m].z = fmaf(xv[2], wq.z, acc[m].z);
                acc[m].w = fmaf(xv[3], wq.w, acc[m].w);
            }
        }
    }

#pragma unroll
    for (int m = 0; m < 4; m++) {
        size_t pix = (size_t)((b * Hn + h0 + m) * Wn + w);
        *(uint2*)(Y + pix * STRIDE + q * 4) = f_to_h4(acc[m].x, acc[m].y, acc[m].z, acc[m].w);
    }
}

// ---------------- kernel 3: SGEMM (f32x2, dup-B smem) + bias + mish, fp16 I/O ----------------
// B stored pre-duplicated per tcx-group at odd pitch (bank-conflict-free dup-pair
// LDS.128 -> directly-usable 64-bit FFMA2 operands, zero movs).
template<int BN_, int TN_, int KTILES>
__global__ __launch_bounds__(256)
void sgemm_mish(const __half* __restrict__ X, int ldX,
                const float* __restrict__ Wp,
                const float* __restrict__ bias,
                __half* __restrict__ Y)
{
    // per-tcx dup-group pitch (floats): TN floats duplicated = 2*TN used
    constexpr int BPITCH = (TN_ == 8) ? 20 : (TN_ == 4) ? 12 : (TN_ == 2) ? 12 : 6;

    __shared__ float As[2][8][128];
    __shared__ float Bs[2][8][16 * BPITCH];

    const int tid = threadIdx.x;
    const int px0 = blockIdx.x * 128;

    const int arow = tid >> 1;
    const int acol = (tid & 1) * 4;
    const __half* aptr = X + (size_t)(px0 + arow) * ldX + acol;

    constexpr int BLOADERS = BN_ * 2;
    const int brow = tid / (BN_ / 4);
    const int bcol = (tid % (BN_ / 4)) * 4;     // 4 consecutive n values
    const float* bptr = Wp + (size_t)brow * BN_ + bcol;

    const int tcx = tid & 15;
    const int tcy = tid >> 4;

    unsigned long long accp[4][TN_];
#pragma unroll
    for (int j = 0; j < 4; j++)
#pragma unroll
        for (int n = 0; n < TN_; n++) accp[j][n] = 0ULL;

    // write 4 B values (bcol..bcol+3) duplicated into swizzled layout
    auto store_b = [&](int buf, float4 v) {
        float vv[4] = {v.x, v.y, v.z, v.w};
        if constexpr (TN_ == 8 || TN_ == 4) {
            // 4 values within one tcx group: base = (bcol/TN)*BPITCH + (bcol%TN)*2
            int g = bcol / TN_;
            int j0 = bcol % TN_;
            float* dst = &Bs[buf][brow][g * BPITCH + j0 * 2];
            *(float4*)(dst)     = make_float4(vv[0], vv[0], vv[1], vv[1]);
            *(float4*)(dst + 4) = make_float4(vv[2], vv[2], vv[3], vv[3]);
        } else if constexpr (TN_ == 2) {
            // spans 2 tcx groups (2 values each)
            int g0 = bcol >> 1;
            *(float4*)&Bs[buf][brow][g0 * BPITCH]       = make_float4(vv[0], vv[0], vv[1], vv[1]);
            *(float4*)&Bs[buf][brow][(g0 + 1) * BPITCH] = make_float4(vv[2], vv[2], vv[3], vv[3]);
        } else {
            // TN_==1: 4 tcx groups, 2 floats each
#pragma unroll
            for (int i = 0; i < 4; i++)
                *(float2*)&Bs[buf][brow][(bcol + i) * BPITCH] = make_float2(vv[i], vv[i]);
        }
    };

    uint2 araw = *(const uint2*)aptr;
    float4 bv;
    if (tid < BLOADERS) bv = *(const float4*)bptr;

    {
        float af[4];
        h4_to_f(araw, af);
        As[0][acol + 0][arow] = af[0];
        As[0][acol + 1][arow] = af[1];
        As[0][acol + 2][arow] = af[2];
        As[0][acol + 3][arow] = af[3];
    }
    if (tid < BLOADERS) store_b(0, bv);
    __syncthreads();

#pragma unroll 1
    for (int kt = 0; kt < KTILES; kt++) {
        const int buf = kt & 1;
        if (kt + 1 < KTILES) {
            araw = *(const uint2*)(aptr + (kt + 1) * 8);
            if (tid < BLOADERS) bv = *(const float4*)(bptr + (size_t)(kt + 1) * 8 * BN_);
        }
#pragma unroll
        for (int kk = 0; kk < 8; kk++) {
            float4 a0 = *(const float4*)&As[buf][kk][tcy * 4];
            float4 a1 = *(const float4*)&As[buf][kk][tcy * 4 + 64];
            unsigned long long ap[4];
            ap[0] = pack2(a0.x, a0.y);
            ap[1] = pack2(a0.z, a0.w);
            ap[2] = pack2(a1.x, a1.y);
            ap[3] = pack2(a1.z, a1.w);

            unsigned long long bd[TN_];
            if constexpr (TN_ == 8) {
#pragma unroll
                for (int g = 0; g < 4; g++) {
                    ulonglong2 t = *(const ulonglong2*)&Bs[buf][kk][tcx * BPITCH + g * 4];
                    bd[2 * g]     = t.x;
                    bd[2 * g + 1] = t.y;
                }
            } else if constexpr (TN_ == 4) {
                ulonglong2 t0 = *(const ulonglong2*)&Bs[buf][kk][tcx * BPITCH];
                ulonglong2 t1 = *(const ulonglong2*)&Bs[buf][kk][tcx * BPITCH + 4];
                bd[0] = t0.x; bd[1] = t0.y; bd[2] = t1.x; bd[3] = t1.y;
            } else if constexpr (TN_ == 2) {
                ulonglong2 t0 = *(const ulonglong2*)&Bs[buf][kk][tcx * BPITCH];
                bd[0] = t0.x; bd[1] = t0.y;
            } else {
                bd[0] = *(const unsigned long long*)&Bs[buf][kk][tcx * BPITCH];
            }
#pragma unroll
            for (int j = 0; j < 4; j++)
#pragma unroll
                for (int n = 0; n < TN_; n++)
                    ffma2(accp[j][n], ap[j], bd[n]);
        }
        if (kt + 1 < KTILES) {
            const int nb = buf ^ 1;
            float af[4];
            h4_to_f(araw, af);
            As[nb][acol + 0][arow] = af[0];
            As[nb][acol + 1][arow] = af[1];
            As[nb][acol + 2][arow] = af[2];
            As[nb][acol + 3][arow] = af[3];
            if (tid < BLOADERS) store_b(nb, bv);
        }
        __syncthreads();
    }

    float acc[8][TN_];
#pragma unroll
    for (int j = 0; j < 4; j++)
#pragma unroll
        for (int n = 0; n < TN_; n++)
            unpack2(accp[j][n], acc[2 * j][n], acc[2 * j + 1][n]);

    float bb[TN_];
    if constexpr (TN_ == 8) {
        float4 t0 = *(const float4*)&bias[tcx * 4];
        float4 t1 = *(const float4*)&bias[tcx * 4 + 64];
        bb[0]=t0.x; bb[1]=t0.y; bb[2]=t0.z; bb[3]=t0.w;
        bb[4]=t1.x; bb[5]=t1.y; bb[6]=t1.z; bb[7]=t1.w;
    } else if constexpr (TN_ == 4) {
        float4 t0 = *(const float4*)&bias[tcx * 4];
        bb[0]=t0.x; bb[1]=t0.y; bb[2]=t0.z; bb[3]=t0.w;
    } else if constexpr (TN_ == 2) {
        float2 t0 = *(const float2*)&bias[tcx * 2];
        bb[0]=t0.x; bb[1]=t0.y;
    } else {
        bb[0] = bias[tcx];
    }

    // NOTE: with dup layout, TN_==8 n-mapping is tcx*8+j (contiguous), others tcx*TN+j
#pragma unroll
    for (int g = 0; g < 2; g++) {
#pragma unroll
        for (int m = 0; m < 4; m++) {
            int px = px0 + tcy * 4 + m + g * 64;
            __half* yr = Y + (size_t)px * BN_;
            float ov[TN_];
            if constexpr (TN_ == 8) {
                // bb was loaded for old mapping (tcx*4 + {0..3}, tcx*4+64 + {0..3});
                // dup layout gives n = tcx*8 + j. Reload bias accordingly.
#pragma unroll
                for (int n = 0; n < 8; n++)
                    ov[n] = mish(acc[g * 4 + m][n] + __ldg(bias + tcx * 8 + n));
                *(uint2*)&yr[tcx * 8]     = f_to_h4(ov[0], ov[1], ov[2], ov[3]);
                *(uint2*)&yr[tcx * 8 + 4] = f_to_h4(ov[4], ov[5], ov[6], ov[7]);
            } else {
#pragma unroll
                for (int n = 0; n < TN_; n++) ov[n] = mish(acc[g * 4 + m][n] + bb[n]);
                if constexpr (TN_ == 4) {
                    *(uint2*)&yr[tcx * 4] = f_to_h4(ov[0], ov[1], ov[2], ov[3]);
                } else if constexpr (TN_ == 2) {
                    __half2 h = __floats2half2_rn(ov[0], ov[1]);
                    *(__half2*)&yr[tcx * 2] = h;
                } else {
                    yr[tcx] = __float2half_rn(ov[0]);
                }
            }
        }
    }
}

// ---------------- kernel 4: BN + 3x3 flow conv + scale (smem-tiled) ----------------
__global__ __launch_bounds__(256)
void final_kernel(const __half* __restrict__ X,
                  const float* __restrict__ gamma, const float* __restrict__ beta,
                  const float* __restrict__ mean,  const float* __restrict__ var,
                  const float* __restrict__ Wf, float* __restrict__ out)
{
    __shared__ float s[10 * 34 * 20];
    __shared__ float sw[9 * 32];

    const int tid = threadIdx.x;
    const int tx  = tid & 31;
    const int ty  = tid >> 5;
    const int bx = blockIdx.x, by = blockIdx.y, b = blockIdx.z;

    float sc[16], sh[16];
#pragma unroll
    for (int c = 0; c < 16; c++) {
        float scale = gamma[c] * rsqrtf(var[c] + BN_EPS);
        sc[c] = scale;
        sh[c] = beta[c] - mean[c] * scale;
    }
    for (int i = tid; i < 288; i += 256) sw[i] = Wf[i];

    for (int i = tid; i < 34 * 10 * 16; i += 256) {
        int c    = i & 15;
        int slot = i >> 4;
        int xs = slot % 34;
        int ys = slot / 34;
        int gx = bx * 32 + xs - 1;
        int gy = by * 8 + ys - 1;
        float v = 0.f;
        if (gx >= 0 && gx < Wn && gy >= 0 && gy < Hn) {
            float xr = __half2float(X[((size_t)((b * Hn + gy) * Wn + gx)) * 16 + c]);
            v = xr * sc[c] + sh[c];
        }
        s[slot * 20 + c] = v;
    }
    __syncthreads();

    float f0 = 0.f, f1 = 0.f;
#pragma unroll
    for (int dy = 0; dy < 3; dy++) {
#pragma unroll
        for (int dx = 0; dx < 3; dx++) {
            const float* base = &s[((ty + dy) * 34 + (tx + dx)) * 20];
            const float* wr = &sw[(dy * 3 + dx) * 32];
#pragma unroll
            for (int g = 0; g < 4; g++) {
                float4 xv = *(const float4*)(base + g * 4);
                f0 = fmaf(xv.x, wr[(g * 4 + 0) * 2],     f0);
                f1 = fmaf(xv.x, wr[(g * 4 + 0) * 2 + 1], f1);
                f0 = fmaf(xv.y, wr[(g * 4 + 1) * 2],     f0);
                f1 = fmaf(xv.y, wr[(g * 4 + 1) * 2 + 1], f1);
                f0 = fmaf(xv.z, wr[(g * 4 + 2) * 2],     f0);
                f1 = fmaf(xv.z, wr[(g * 4 + 2) * 2 + 1], f1);
                f0 = fmaf(xv.w, wr[(g * 4 + 3) * 2],     f0);
                f1 = fmaf(xv.w, wr[(g * 4 + 3) * 2 + 1], f1);
            }
        }
    }

    size_t pix = (size_t)(b * Hn + by * 8 + ty) * Wn + bx * 32 + tx;
    out[pix * 2 + 0] = FLOW_SCALE * f0;
    out[pix * 2 + 1] = FLOW_SCALE * f1;
}

// ---------------- launch ----------------
extern "C" void kernel_launch(void* const* d_in, const int* in_sizes, int n_in,
                              void* d_out, int out_size)
{
    const float* prv   = (const float*)d_in[0];
    const float* nxt   = (const float*)d_in[1];
    const float* dw0   = (const float*)d_in[2];
    const float* pw0   = (const float*)d_in[3];
    const float* b0    = (const float*)d_in[4];
    const float* dw1   = (const float*)d_in[5];
    const float* pw1   = (const float*)d_in[6];
    const float* b1    = (const float*)d_in[7];
    const float* dw2   = (const float*)d_in[8];
    const float* pw2   = (const float*)d_in[9];
    const float* b2    = (const float*)d_in[10];
    const float* dw3   = (const float*)d_in[11];
    const float* pw3   = (const float*)d_in[12];
    const float* b3    = (const float*)d_in[13];
    const float* bng   = (const float*)d_in[14];
    const float* bnb   = (const float*)d_in[15];
    const float* bnm   = (const float*)d_in[16];
    const float* bnv   = (const float*)d_in[17];
    const float* flw   = (const float*)d_in[18];
    float* out = (float*)d_out;

    __half *A = nullptr, *Bb = nullptr;
    float *W0 = nullptr, *PW0 = nullptr;
    cudaGetSymbolAddress((void**)&A,   g_bufA);
    cudaGetSymbolAddress((void**)&Bb,  g_bufB);
    cudaGetSymbolAddress((void**)&W0,  g_dw0pad);
    cudaGetSymbolAddress((void**)&PW0, g_pw0pad);

    pad_w_kernel<<<(P0 * 128 + 255) / 256, 256>>>(dw0, pw0);

    // cost volume + concat -> A [NPIX, 216] fp16
    {
        dim3 grid(Wn / 32, Hn / 8, Bn);
        cost_kernel<0, 5><<<grid, 128>>>(prv, nxt, A);
        cost_kernel<5, 4><<<grid, 128>>>(prv, nxt, A);
    }

    // layer 0
    dw4y_kernel<54, P0, P0><<<((NPIX / 4) * 54 + 255) / 256, 256>>>(A, W0, Bb);
    sgemm_mish<128, 8, P0 / 8><<<NPIX / 128, 256>>>(Bb, P0, PW0, b0, A);
    // layer 1
    dw4y_kernel<32, 128, 128><<<((NPIX / 4) * 32 + 255) / 256, 256>>>(A, dw1, Bb);
    sgemm_mish<64, 4, 16><<<NPIX / 128, 256>>>(Bb, 128, pw1, b1, A);
    // layer 2
    dw4y_kernel<16, 64, 64><<<((NPIX / 4) * 16 + 255) / 256, 256>>>(A, dw2, Bb);
    sgemm_mish<32, 2, 8><<<NPIX / 128, 256>>>(Bb, 64, pw2, b2, A);
    // layer 3
    dw4y_kernel<8, 32, 32><<<((NPIX / 4) * 8 + 255) / 256, 256>>>(A, dw3, Bb);
    sgemm_mish<16, 1, 4><<<NPIX / 128, 256>>>(Bb, 32, pw3, b3, A);

    // BN + flow conv + scale (tiled)
    {
        dim3 grid(Wn / 32, Hn / 8, Bn);
        final_kernel<<<grid, 256>>>(A, bng, bnb, bnm, bnv, flw, out);
    }
}

// round 16
// speedup vs baseline: 1.1938x; 1.1938x over previous
#include <cuda_runtime.h>
#include <cuda_fp16.h>
#include <math.h>

// ---------------- problem constants ----------------
#define Bn 8
#define Hn 192
#define Wn 192
#define Cn 64
#define NPIX (Bn*Hn*Wn)          // 294912
#define CV 81
#define CIN0 209
#define P0 216                    // padded channel stride (27 * 8)
#define FLOW_SCALE 271.52900393598527f
#define BN_EPS 1e-3f

// ---------------- scratch (activations in fp16) ----------------
__device__ __half g_bufA[(size_t)NPIX * P0];
__device__ __half g_bufB[(size_t)NPIX * P0];
__device__ float g_dw0pad[9 * P0];
__device__ float g_pw0pad[P0 * 128];

// mish via identity: tanh(softplus(x)) = (s^2+2s)/(s^2+2s+2), s=e^x.
__device__ __forceinline__ float mish(float x) {
    float s = __expf(x);
    float t = s * (s + 2.f);
    float r = x * __fdividef(t, t + 2.f);
    return (x > 15.f) ? x : r;
}

// ---------------- packed f32x2 helpers ----------------
__device__ __forceinline__ unsigned long long pack2(float x, float y) {
    unsigned long long r;
    asm("mov.b64 %0, {%1, %2};" : "=l"(r) : "f"(x), "f"(y));
    return r;
}
__device__ __forceinline__ void unpack2(unsigned long long v, float& x, float& y) {
    asm("mov.b64 {%0, %1}, %2;" : "=f"(x), "=f"(y) : "l"(v));
}
__device__ __forceinline__ void ffma2(unsigned long long& c, unsigned long long a, unsigned long long b) {
    asm("fma.rn.f32x2 %0, %1, %2, %0;" : "+l"(c) : "l"(a), "l"(b));
}

// half4 <-> float helpers
__device__ __forceinline__ void h4_to_f(const uint2 raw, float* f) {
    __half2 h0 = *(const __half2*)&raw.x;
    __half2 h1 = *(const __half2*)&raw.y;
    float2 a = __half22float2(h0), b = __half22float2(h1);
    f[0] = a.x; f[1] = a.y; f[2] = b.x; f[3] = b.y;
}
__device__ __forceinline__ uint2 f_to_h4(float a, float b, float c, float d) {
    __half2 h0 = __floats2half2_rn(a, b);
    __half2 h1 = __floats2half2_rn(c, d);
    uint2 r;
    r.x = *(const unsigned*)&h0;
    r.y = *(const unsigned*)&h1;
    return r;
}

// ---------------- kernel 0: pad dw0 + pw0 weights ----------------
__global__ void pad_w_kernel(const float* __restrict__ dw0, const float* __restrict__ pw0)
{
    int idx = blockIdx.x * blockDim.x + threadIdx.x;
    if (idx < 9 * P0) {
        int c = idx % P0;
        int k = idx / P0;
        g_dw0pad[idx] = (c < CIN0) ? dw0[k * CIN0 + c] : 0.f;
    }
    if (idx < P0 * 128) {
        int n = idx % 128;
        int k = idx / 128;
        g_pw0pad[idx] = (k < CIN0) ? pw0[k * 128 + n] : 0.f;
    }
}

// ---------------- kernel 1: cost volume (+ concat fold in DXB==0 pass) ----------------
// smem ALIASED: sbuf (staging) and sout (store transpose) share one array —
// their live ranges are disjoint (sbuf fully read before sout is written).
// 88.5 KB -> 46.2 KB static smem: 2 -> 4 blocks/SM.
template<int DXB, int NDX>
__global__ __launch_bounds__(128)
void cost_kernel(const float* __restrict__ prv, const float* __restrict__ nxt,
                 __half* __restrict__ x0)
{
    constexpr int SBUF_N = 16 * 661;          // 10576
    constexpr int SOUT_N = NDX * 9 * 257;     // 11565 (NDX=5) / 9252 (NDX=4)
    __shared__ float sh[(SBUF_N > SOUT_N) ? SBUF_N : SOUT_N];
    float* sbuf = sh;
    float* sout = sh;

    const int tid  = threadIdx.x;
    const int lane = tid & 31;
    const int wp   = tid >> 5;
    const int bx = blockIdx.x, by = blockIdx.y, b = blockIdx.z;

    const int x    = bx * 32 + lane;
    const int y0   = by * 8 + wp * 2;
    const size_t pix0 = (size_t)(b * Hn + y0) * Wn + x;
    const size_t pix1 = pix0 + Wn;

    float acc0[NDX * 9], acc1[NDX * 9];
#pragma unroll
    for (int t = 0; t < NDX * 9; t++) { acc0[t] = 0.f; acc1[t] = 0.f; }

#pragma unroll 1
    for (int chp = 0; chp < 4; chp++) {
        __syncthreads();
#pragma unroll 4
        for (int k = 0; k < 80; k++) {
            int i = tid + k * 128;
            int c = i & 15;
            int rest = i >> 4;
            int xs = rest % 40;
            int r  = rest / 40;
            int gy = by * 8 + r - 4;
            int gx = bx * 32 + xs - 4;
            float v = 0.f;
            if (gy >= 0 && gy < Hn && gx >= 0 && gx < Wn)
                v = nxt[((size_t)(b * Hn + gy) * Wn + gx) * Cn + chp * 16 + c];
            sbuf[c * 661 + r * 41 + xs] = v;
        }
        __syncthreads();

#pragma unroll 1
        for (int c4 = 0; c4 < 4; c4++) {
            float4 pa = *(const float4*)(prv + pix0 * Cn + chp * 16 + c4 * 4);
            float4 pb = *(const float4*)(prv + pix1 * Cn + chp * 16 + c4 * 4);
            float pav[4] = {pa.x, pa.y, pa.z, pa.w};
            float pbv[4] = {pb.x, pb.y, pb.z, pb.w};
#pragma unroll
            for (int cc = 0; cc < 4; cc++) {
                const float* splane = &sbuf[(c4 * 4 + cc) * 661];
#pragma unroll
                for (int rr = 0; rr < 10; rr++) {
                    const float* q = &splane[(wp * 2 + rr) * 41 + lane + DXB];
#pragma unroll
                    for (int d = 0; d < NDX; d++) {
                        float qv = q[d];
                        if (rr < 9)  acc0[rr * NDX + d]       = fmaf(pav[cc], qv, acc0[rr * NDX + d]);
                        if (rr >= 1) acc1[(rr - 1) * NDX + d] = fmaf(pbv[cc], qv, acc1[(rr - 1) * NDX + d]);
                    }
                }
            }
        }
    }

    __syncthreads();   // all sbuf reads done before aliased sout writes
    const int pl0 = wp * 64 + lane;
#pragma unroll
    for (int t = 0; t < NDX * 9; t++) {
        float v0 = acc0[t] * (1.f / 64.f); v0 = (v0 > 0.f) ? v0 : 0.1f * v0;
        float v1 = acc1[t] * (1.f / 64.f); v1 = (v1 > 0.f) ? v1 : 0.1f * v1;
        sout[t * 257 + pl0]      = v0;
        sout[t * 257 + pl0 + 32] = v1;
    }
    __syncthreads();

    const int TOT = 256 * NDX * 9;
    for (int i = tid; i < TOT; i += 128) {
        int px = i / (NDX * 9);
        int t  = i % (NDX * 9);
        int dy = t / NDX, d = t % NDX;
        int yl = px >> 5, xx = px & 31;
        size_t pix = (size_t)(b * Hn + by * 8 + yl) * Wn + bx * 32 + xx;
        x0[pix * P0 + dy * 9 + DXB + d] = __float2half_rn(sout[t * 257 + px]);
    }

    if (DXB == 0) {
        for (int j = tid; j < 256 * 64; j += 128) {
            int px = j >> 6, c = j & 63;
            int yl = px >> 5, xx = px & 31;
            size_t pix = (size_t)(b * Hn + by * 8 + yl) * Wn + bx * 32 + xx;
            x0[pix * P0 + CV + c]      = __float2half_rn(prv[pix * Cn + c]);
            x0[pix * P0 + CV + 64 + c] = __float2half_rn(nxt[pix * Cn + c]);
            if (c >= 57) x0[pix * P0 + 152 + c] = __float2half_rn(0.f);   // 209..215
        }
    }
}

// ---------------- kernel 2: depthwise 3x3, half4 channels, 4 y-outputs/thread ----------------
template<int QUADS, int STRIDE, int WSTRIDE>
__global__ __launch_bounds__(256, 4)
void dw4y_kernel(const __half* __restrict__ X, const float* __restrict__ Wd,
                 __half* __restrict__ Y)
{
    int idx = blockIdx.x * blockDim.x + threadIdx.x;
    if (idx >= (NPIX / 4) * QUADS) return;
    int q    = idx % QUADS;
    int rest = idx / QUADS;
    int w    = rest % Wn;
    int rest2 = rest / Wn;
    int hg   = rest2 % (Hn / 4);
    int b    = rest2 / (Hn / 4);
    const int h0 = hg * 4;

    float4 wv[9];
#pragma unroll
    for (int t = 0; t < 9; t++)
        wv[t] = *(const float4*)(Wd + t * WSTRIDE + q * 4);

    float4 acc[4];
#pragma unroll
    for (int m = 0; m < 4; m++) acc[m] = make_float4(0.f, 0.f, 0.f, 0.f);

    const bool wl = (w - 1 >= 0), wr = (w + 1 < Wn);

#pragma unroll
    for (int r = 0; r < 6; r++) {
        int hh = h0 + r - 1;
        if (hh < 0 || hh >= Hn) continue;
        const __half* rowp = X + ((size_t)((b * Hn + hh) * Wn + w)) * STRIDE + q * 4;
#pragma unroll
        for (int kx = 0; kx < 3; kx++) {
            if (kx == 0 && !wl) continue;
            if (kx == 2 && !wr) continue;
            uint2 raw = *(const uint2*)(rowp + (kx - 1) * STRIDE);
            float xv[4];
            h4_to_f(raw, xv);
#pragma unroll
            for (int m = 0; m < 4; m++) {
                int ky = r - m;
                if (ky < 0 || ky > 2) continue;
                float4 wq = wv[ky * 3 + kx];
                acc[m].x = fmaf(xv[0], wq.x, acc[m].x);
                acc[m].y = fmaf(xv[1], wq.y, acc[m].y);
                acc[m].z = fmaf(xv[2], wq.z, acc[m].z);
                acc[m].w = fmaf(xv[3], wq.w, acc[m].w);
            }
        }
    }

#pragma unroll
    for (int m = 0; m < 4; m++) {
        size_t pix = (size_t)((b * Hn + h0 + m) * Wn + w);
        *(uint2*)(Y + pix * STRIDE + q * 4) = f_to_h4(acc[m].x, acc[m].y, acc[m].z, acc[m].w);
    }
}

// ---------------- kernel 3: SGEMM (f32x2) + bias + mish, fp16 I/O (R14 proven) ----------------
template<int BN_, int TN_, int KTILES>
__global__ __launch_bounds__(256)
void sgemm_mish(const __half* __restrict__ X, int ldX,
                const float* __restrict__ Wp,
                const float* __restrict__ bias,
                __half* __restrict__ Y)
{
    __shared__ float As[2][8][128];
    __shared__ float Bs[2][8][BN_];

    const int tid = threadIdx.x;
    const int px0 = blockIdx.x * 128;

    const int arow = tid >> 1;
    const int acol = (tid & 1) * 4;
    const __half* aptr = X + (size_t)(px0 + arow) * ldX + acol;

    constexpr int BLOADERS = BN_ * 2;
    const int brow = tid / (BN_ / 4);
    const int bcol = (tid % (BN_ / 4)) * 4;
    const float* bptr = Wp + (size_t)brow * BN_ + bcol;

    const int tcx = tid & 15;
    const int tcy = tid >> 4;

    unsigned long long accp[4][TN_];
#pragma unroll
    for (int j = 0; j < 4; j++)
#pragma unroll
        for (int n = 0; n < TN_; n++) accp[j][n] = 0ULL;

    uint2 araw = *(const uint2*)aptr;
    float4 bv;
    if (tid < BLOADERS) bv = *(const float4*)bptr;

    {
        float af[4];
        h4_to_f(araw, af);
        As[0][acol + 0][arow] = af[0];
        As[0][acol + 1][arow] = af[1];
        As[0][acol + 2][arow] = af[2];
        As[0][acol + 3][arow] = af[3];
    }
    if (tid < BLOADERS) *(float4*)&Bs[0][brow][bcol] = bv;
    __syncthreads();

#pragma unroll 1
    for (int kt = 0; kt < KTILES; kt++) {
        const int buf = kt & 1;
        if (kt + 1 < KTILES) {
            araw = *(const uint2*)(aptr + (kt + 1) * 8);
            if (tid < BLOADERS) bv = *(const float4*)(bptr + (size_t)(kt + 1) * 8 * BN_);
        }
#pragma unroll
        for (int kk = 0; kk < 8; kk++) {
            float4 a0 = *(const float4*)&As[buf][kk][tcy * 4];
            float4 a1 = *(const float4*)&As[buf][kk][tcy * 4 + 64];
            unsigned long long ap[4];
            ap[0] = pack2(a0.x, a0.y);
            ap[1] = pack2(a0.z, a0.w);
            ap[2] = pack2(a1.x, a1.y);
            ap[3] = pack2(a1.z, a1.w);

            float br[TN_];
            if constexpr (TN_ == 8) {
                float4 b0 = *(const float4*)&Bs[buf][kk][tcx * 4];
                float4 b1 = *(const float4*)&Bs[buf][kk][tcx * 4 + 64];
                br[0] = b0.x; br[1] = b0.y; br[2] = b0.z; br[3] = b0.w;
                br[4] = b1.x; br[5] = b1.y; br[6] = b1.z; br[7] = b1.w;
            } else if constexpr (TN_ == 4) {
                float4 b0 = *(const float4*)&Bs[buf][kk][tcx * 4];
                br[0] = b0.x; br[1] = b0.y; br[2] = b0.z; br[3] = b0.w;
            } else if constexpr (TN_ == 2) {
                float2 b0 = *(const float2*)&Bs[buf][kk][tcx * 2];
                br[0] = b0.x; br[1] = b0.y;
            } else {
                br[0] = Bs[buf][kk][tcx];
            }
            unsigned long long bd[TN_];
#pragma unroll
            for (int n = 0; n < TN_; n++) bd[n] = pack2(br[n], br[n]);
#pragma unroll
            for (int j = 0; j < 4; j++)
#pragma unroll
                for (int n = 0; n < TN_; n++)
                    ffma2(accp[j][n], ap[j], bd[n]);
        }
        if (kt + 1 < KTILES) {
            const int nb = buf ^ 1;
            float af[4];
            h4_to_f(araw, af);
            As[nb][acol + 0][arow] = af[0];
            As[nb][acol + 1][arow] = af[1];
            As[nb][acol + 2][arow] = af[2];
            As[nb][acol + 3][arow] = af[3];
            if (tid < BLOADERS) *(float4*)&Bs[nb][brow][bcol] = bv;
        }
        __syncthreads();
    }

    float acc[8][TN_];
#pragma unroll
    for (int j = 0; j < 4; j++)
#pragma unroll
        for (int n = 0; n < TN_; n++)
            unpack2(accp[j][n], acc[2 * j][n], acc[2 * j + 1][n]);

    float bb[TN_];
    if constexpr (TN_ == 8) {
        float4 t0 = *(const float4*)&bias[tcx * 4];
        float4 t1 = *(const float4*)&bias[tcx * 4 + 64];
        bb[0]=t0.x; bb[1]=t0.y; bb[2]=t0.z; bb[3]=t0.w;
        bb[4]=t1.x; bb[5]=t1.y; bb[6]=t1.z; bb[7]=t1.w;
    } else if constexpr (TN_ == 4) {
        float4 t0 = *(const float4*)&bias[tcx * 4];
        bb[0]=t0.x; bb[1]=t0.y; bb[2]=t0.z; bb[3]=t0.w;
    } else if constexpr (TN_ == 2) {
        float2 t0 = *(const float2*)&bias[tcx * 2];
        bb[0]=t0.x; bb[1]=t0.y;
    } else {
        bb[0] = bias[tcx];
    }

#pragma unroll
    for (int g = 0; g < 2; g++) {
#pragma unroll
        for (int m = 0; m < 4; m++) {
            int px = px0 + tcy * 4 + m + g * 64;
            __half* yr = Y + (size_t)px * BN_;
            float ov[TN_];
#pragma unroll
            for (int n = 0; n < TN_; n++) ov[n] = mish(acc[g * 4 + m][n] + bb[n]);
            if constexpr (TN_ == 8) {
                *(uint2*)&yr[tcx * 4]      = f_to_h4(ov[0], ov[1], ov[2], ov[3]);
                *(uint2*)&yr[tcx * 4 + 64] = f_to_h4(ov[4], ov[5], ov[6], ov[7]);
            } else if constexpr (TN_ == 4) {
                *(uint2*)&yr[tcx * 4] = f_to_h4(ov[0], ov[1], ov[2], ov[3]);
            } else if constexpr (TN_ == 2) {
                __half2 h = __floats2half2_rn(ov[0], ov[1]);
                *(__half2*)&yr[tcx * 2] = h;
            } else {
                yr[tcx] = __float2half_rn(ov[0]);
            }
        }
    }
}

// ---------------- kernel 4: BN + 3x3 flow conv + scale (smem-tiled) ----------------
__global__ __launch_bounds__(256)
void final_kernel(const __half* __restrict__ X,
                  const float* __restrict__ gamma, const float* __restrict__ beta,
                  const float* __restrict__ mean,  const float* __restrict__ var,
                  const float* __restrict__ Wf, float* __restrict__ out)
{
    __shared__ float s[10 * 34 * 20];
    __shared__ float sw[9 * 32];

    const int tid = threadIdx.x;
    const int tx  = tid & 31;
    const int ty  = tid >> 5;
    const int bx = blockIdx.x, by = blockIdx.y, b = blockIdx.z;

    float sc[16], sh2[16];
#pragma unroll
    for (int c = 0; c < 16; c++) {
        float scale = gamma[c] * rsqrtf(var[c] + BN_EPS);
        sc[c] = scale;
        sh2[c] = beta[c] - mean[c] * scale;
    }
    for (int i = tid; i < 288; i += 256) sw[i] = Wf[i];

    for (int i = tid; i < 34 * 10 * 16; i += 256) {
        int c    = i & 15;
        int slot = i >> 4;
        int xs = slot % 34;
        int ys = slot / 34;
        int gx = bx * 32 + xs - 1;
        int gy = by * 8 + ys - 1;
        float v = 0.f;
        if (gx >= 0 && gx < Wn && gy >= 0 && gy < Hn) {
            float xr = __half2float(X[((size_t)((b * Hn + gy) * Wn + gx)) * 16 + c]);
            v = xr * sc[c] + sh2[c];
        }
        s[slot * 20 + c] = v;
    }
    __syncthreads();

    float f0 = 0.f, f1 = 0.f;
#pragma unroll
    for (int dy = 0; dy < 3; dy++) {
#pragma unroll
        for (int dx = 0; dx < 3; dx++) {
            const float* base = &s[((ty + dy) * 34 + (tx + dx)) * 20];
            const float* wr = &sw[(dy * 3 + dx) * 32];
#pragma unroll
            for (int g = 0; g < 4; g++) {
                float4 xv = *(const float4*)(base + g * 4);
                f0 = fmaf(xv.x, wr[(g * 4 + 0) * 2],     f0);
                f1 = fmaf(xv.x, wr[(g * 4 + 0) * 2 + 1], f1);
                f0 = fmaf(xv.y, wr[(g * 4 + 1) * 2],     f0);
                f1 = fmaf(xv.y, wr[(g * 4 + 1) * 2 + 1], f1);
                f0 = fmaf(xv.z, wr[(g * 4 + 2) * 2],     f0);
                f1 = fmaf(xv.z, wr[(g * 4 + 2) * 2 + 1], f1);
                f0 = fmaf(xv.w, wr[(g * 4 + 3) * 2],     f0);
                f1 = fmaf(xv.w, wr[(g * 4 + 3) * 2 + 1], f1);
            }
        }
    }

    size_t pix = (size_t)(b * Hn + by * 8 + ty) * Wn + bx * 32 + tx;
    out[pix * 2 + 0] = FLOW_SCALE * f0;
    out[pix * 2 + 1] = FLOW_SCALE * f1;
}

// ---------------- launch ----------------
extern "C" void kernel_launch(void* const* d_in, const int* in_sizes, int n_in,
                              void* d_out, int out_size)
{
    const float* prv   = (const float*)d_in[0];
    const float* nxt   = (const float*)d_in[1];
    const float* dw0   = (const float*)d_in[2];
    const float* pw0   = (const float*)d_in[3];
    const float* b0    = (const float*)d_in[4];
    const float* dw1   = (const float*)d_in[5];
    const float* pw1   = (const float*)d_in[6];
    const float* b1    = (const float*)d_in[7];
    const float* dw2   = (const float*)d_in[8];
    const float* pw2   = (const float*)d_in[9];
    const float* b2    = (const float*)d_in[10];
    const float* dw3   = (const float*)d_in[11];
    const float* pw3   = (const float*)d_in[12];
    const float* b3    = (const float*)d_in[13];
    const float* bng   = (const float*)d_in[14];
    const float* bnb   = (const float*)d_in[15];
    const float* bnm   = (const float*)d_in[16];
    const float* bnv   = (const float*)d_in[17];
    const float* flw   = (const float*)d_in[18];
    float* out = (float*)d_out;

    __half *A = nullptr, *Bb = nullptr;
    float *W0 = nullptr, *PW0 = nullptr;
    cudaGetSymbolAddress((void**)&A,   g_bufA);
    cudaGetSymbolAddress((void**)&Bb,  g_bufB);
    cudaGetSymbolAddress((void**)&W0,  g_dw0pad);
    cudaGetSymbolAddress((void**)&PW0, g_pw0pad);

    pad_w_kernel<<<(P0 * 128 + 255) / 256, 256>>>(dw0, pw0);

    // cost volume + concat -> A [NPIX, 216] fp16
    {
        dim3 grid(Wn / 32, Hn / 8, Bn);
        cost_kernel<0, 5><<<grid, 128>>>(prv, nxt, A);
        cost_kernel<5, 4><<<grid, 128>>>(prv, nxt, A);
    }

    // layer 0
    dw4y_kernel<54, P0, P0><<<((NPIX / 4) * 54 + 255) / 256, 256>>>(A, W0, Bb);
    sgemm_mish<128, 8, P0 / 8><<<NPIX / 128, 256>>>(Bb, P0, PW0, b0, A);
    // layer 1
    dw4y_kernel<32, 128, 128><<<((NPIX / 4) * 32 + 255) / 256, 256>>>(A, dw1, Bb);
    sgemm_mish<64, 4, 16><<<NPIX / 128, 256>>>(Bb, 128, pw1, b1, A);
    // layer 2
    dw4y_kernel<16, 64, 64><<<((NPIX / 4) * 16 + 255) / 256, 256>>>(A, dw2, Bb);
    sgemm_mish<32, 2, 8><<<NPIX / 128, 256>>>(Bb, 64, pw2, b2, A);
    // layer 3
    dw4y_kernel<8, 32, 32><<<((NPIX / 4) * 8 + 255) / 256, 256>>>(A, dw3, Bb);
    sgemm_mish<16, 1, 4><<<NPIX / 128, 256>>>(Bb, 32, pw3, b3, A);

    // BN + flow conv + scale (tiled)
    {
        dim3 grid(Wn / 32, Hn / 8, Bn);
        final_kernel<<<grid, 256>>>(A, bng, bnb, bnm, bnv, flw, out);
    }
}

// round 17
// speedup vs baseline: 1.2155x; 1.0181x over previous
#include <cuda_runtime.h>
#include <cuda_fp16.h>
#include <math.h>

// ---------------- problem constants ----------------
#define Bn 8
#define Hn 192
#define Wn 192
#define Cn 64
#define NPIX (Bn*Hn*Wn)          // 294912
#define CV 81
#define CIN0 209
#define P0 224                    // padded channel stride (14 * 16)
#define FLOW_SCALE 271.52900393598527f
#define BN_EPS 1e-3f

// ---------------- scratch (activations in fp16) ----------------
__device__ __half g_bufA[(size_t)NPIX * P0];
__device__ __half g_bufB[(size_t)NPIX * P0];
__device__ float g_dw0pad[9 * P0];
__device__ float g_pw0pad[P0 * 128];

// mish via identity: tanh(softplus(x)) = (s^2+2s)/(s^2+2s+2), s=e^x.
__device__ __forceinline__ float mish(float x) {
    float s = __expf(x);
    float t = s * (s + 2.f);
    float r = x * __fdividef(t, t + 2.f);
    return (x > 15.f) ? x : r;
}

// ---------------- packed f32x2 helpers ----------------
__device__ __forceinline__ unsigned long long pack2(float x, float y) {
    unsigned long long r;
    asm("mov.b64 %0, {%1, %2};" : "=l"(r) : "f"(x), "f"(y));
    return r;
}
__device__ __forceinline__ void unpack2(unsigned long long v, float& x, float& y) {
    asm("mov.b64 {%0, %1}, %2;" : "=f"(x), "=f"(y) : "l"(v));
}
__device__ __forceinline__ void ffma2(unsigned long long& c, unsigned long long a, unsigned long long b) {
    asm("fma.rn.f32x2 %0, %1, %2, %0;" : "+l"(c) : "l"(a), "l"(b));
}

// half4 <-> float helpers
__device__ __forceinline__ void h4_to_f(const uint2 raw, float* f) {
    __half2 h0 = *(const __half2*)&raw.x;
    __half2 h1 = *(const __half2*)&raw.y;
    float2 a = __half22float2(h0), b = __half22float2(h1);
    f[0] = a.x; f[1] = a.y; f[2] = b.x; f[3] = b.y;
}
__device__ __forceinline__ uint2 f_to_h4(float a, float b, float c, float d) {
    __half2 h0 = __floats2half2_rn(a, b);
    __half2 h1 = __floats2half2_rn(c, d);
    uint2 r;
    r.x = *(const unsigned*)&h0;
    r.y = *(const unsigned*)&h1;
    return r;
}

// ---------------- kernel 0: pad dw0 + pw0 weights ----------------
__global__ void pad_w_kernel(const float* __restrict__ dw0, const float* __restrict__ pw0)
{
    int idx = blockIdx.x * blockDim.x + threadIdx.x;
    if (idx < 9 * P0) {
        int c = idx % P0;
        int k = idx / P0;
        g_dw0pad[idx] = (c < CIN0) ? dw0[k * CIN0 + c] : 0.f;
    }
    if (idx < P0 * 128) {
        int n = idx % 128;
        int k = idx / 128;
        g_pw0pad[idx] = (k < CIN0) ? pw0[k * 128 + n] : 0.f;
    }
}

// ---------------- kernel 1: cost volume (+ concat fold in DXB==0 pass) ----------------
// smem aliased (sbuf/sout live ranges disjoint): 4 blocks/SM.
template<int DXB, int NDX>
__global__ __launch_bounds__(128)
void cost_kernel(const float* __restrict__ prv, const float* __restrict__ nxt,
                 __half* __restrict__ x0)
{
    constexpr int SBUF_N = 16 * 661;
    constexpr int SOUT_N = NDX * 9 * 257;
    __shared__ float sh[(SBUF_N > SOUT_N) ? SBUF_N : SOUT_N];
    float* sbuf = sh;
    float* sout = sh;

    const int tid  = threadIdx.x;
    const int lane = tid & 31;
    const int wp   = tid >> 5;
    const int bx = blockIdx.x, by = blockIdx.y, b = blockIdx.z;

    const int x    = bx * 32 + lane;
    const int y0   = by * 8 + wp * 2;
    const size_t pix0 = (size_t)(b * Hn + y0) * Wn + x;
    const size_t pix1 = pix0 + Wn;

    float acc0[NDX * 9], acc1[NDX * 9];
#pragma unroll
    for (int t = 0; t < NDX * 9; t++) { acc0[t] = 0.f; acc1[t] = 0.f; }

#pragma unroll 1
    for (int chp = 0; chp < 4; chp++) {
        __syncthreads();
#pragma unroll 4
        for (int k = 0; k < 80; k++) {
            int i = tid + k * 128;
            int c = i & 15;
            int rest = i >> 4;
            int xs = rest % 40;
            int r  = rest / 40;
            int gy = by * 8 + r - 4;
            int gx = bx * 32 + xs - 4;
            float v = 0.f;
            if (gy >= 0 && gy < Hn && gx >= 0 && gx < Wn)
                v = nxt[((size_t)(b * Hn + gy) * Wn + gx) * Cn + chp * 16 + c];
            sbuf[c * 661 + r * 41 + xs] = v;
        }
        __syncthreads();

#pragma unroll 1
        for (int c4 = 0; c4 < 4; c4++) {
            float4 pa = *(const float4*)(prv + pix0 * Cn + chp * 16 + c4 * 4);
            float4 pb = *(const float4*)(prv + pix1 * Cn + chp * 16 + c4 * 4);
            float pav[4] = {pa.x, pa.y, pa.z, pa.w};
            float pbv[4] = {pb.x, pb.y, pb.z, pb.w};
#pragma unroll
            for (int cc = 0; cc < 4; cc++) {
                const float* splane = &sbuf[(c4 * 4 + cc) * 661];
#pragma unroll
                for (int rr = 0; rr < 10; rr++) {
                    const float* q = &splane[(wp * 2 + rr) * 41 + lane + DXB];
#pragma unroll
                    for (int d = 0; d < NDX; d++) {
                        float qv = q[d];
                        if (rr < 9)  acc0[rr * NDX + d]       = fmaf(pav[cc], qv, acc0[rr * NDX + d]);
                        if (rr >= 1) acc1[(rr - 1) * NDX + d] = fmaf(pbv[cc], qv, acc1[(rr - 1) * NDX + d]);
                    }
                }
            }
        }
    }

    __syncthreads();
    const int pl0 = wp * 64 + lane;
#pragma unroll
    for (int t = 0; t < NDX * 9; t++) {
        float v0 = acc0[t] * (1.f / 64.f); v0 = (v0 > 0.f) ? v0 : 0.1f * v0;
        float v1 = acc1[t] * (1.f / 64.f); v1 = (v1 > 0.f) ? v1 : 0.1f * v1;
        sout[t * 257 + pl0]      = v0;
        sout[t * 257 + pl0 + 32] = v1;
    }
    __syncthreads();

    const int TOT = 256 * NDX * 9;
    for (int i = tid; i < TOT; i += 128) {
        int px = i / (NDX * 9);
        int t  = i % (NDX * 9);
        int dy = t / NDX, d = t % NDX;
        int yl = px >> 5, xx = px & 31;
        size_t pix = (size_t)(b * Hn + by * 8 + yl) * Wn + bx * 32 + xx;
        x0[pix * P0 + dy * 9 + DXB + d] = __float2half_rn(sout[t * 257 + px]);
    }

    if (DXB == 0) {
        for (int j = tid; j < 256 * 64; j += 128) {
            int px = j >> 6, c = j & 63;
            int yl = px >> 5, xx = px & 31;
            size_t pix = (size_t)(b * Hn + by * 8 + yl) * Wn + bx * 32 + xx;
            x0[pix * P0 + CV + c]      = __float2half_rn(prv[pix * Cn + c]);
            x0[pix * P0 + CV + 64 + c] = __float2half_rn(nxt[pix * Cn + c]);
            if (c >= 49) x0[pix * P0 + 160 + c] = __float2half_rn(0.f);   // 209..223
        }
    }
}

// ---------------- kernel 2: depthwise 3x3, half4 channels, 4 y-outputs/thread ----------------
template<int QUADS, int STRIDE, int WSTRIDE>
__global__ __launch_bounds__(256, 4)
void dw4y_kernel(const __half* __restrict__ X, const float* __restrict__ Wd,
                 __half* __restrict__ Y)
{
    int idx = blockIdx.x * blockDim.x + threadIdx.x;
    if (idx >= (NPIX / 4) * QUADS) return;
    int q    = idx % QUADS;
    int rest = idx / QUADS;
    int w    = rest % Wn;
    int rest2 = rest / Wn;
    int hg   = rest2 % (Hn / 4);
    int b    = rest2 / (Hn / 4);
    const int h0 = hg * 4;

    float4 wv[9];
#pragma unroll
    for (int t = 0; t < 9; t++)
        wv[t] = *(const float4*)(Wd + t * WSTRIDE + q * 4);

    float4 acc[4];
#pragma unroll
    for (int m = 0; m < 4; m++) acc[m] = make_float4(0.f, 0.f, 0.f, 0.f);

    const bool wl = (w - 1 >= 0), wr = (w + 1 < Wn);

#pragma unroll
    for (int r = 0; r < 6; r++) {
        int hh = h0 + r - 1;
        if (hh < 0 || hh >= Hn) continue;
        const __half* rowp = X + ((size_t)((b * Hn + hh) * Wn + w)) * STRIDE + q * 4;
#pragma unroll
        for (int kx = 0; kx < 3; kx++) {
            if (kx == 0 && !wl) continue;
            if (kx == 2 && !wr) continue;
            uint2 raw = *(const uint2*)(rowp + (kx - 1) * STRIDE);
            float xv[4];
            h4_to_f(raw, xv);
#pragma unroll
            for (int m = 0; m < 4; m++) {
                int ky = r - m;
                if (ky < 0 || ky > 2) continue;
                float4 wq = wv[ky * 3 + kx];
                acc[m].x = fmaf(xv[0], wq.x, acc[m].x);
                acc[m].y = fmaf(xv[1], wq.y, acc[m].y);
                acc[m].z = fmaf(xv[2], wq.z, acc[m].z);
                acc[m].w = fmaf(xv[3], wq.w, acc[m].w);
            }
        }
    }

#pragma unroll
    for (int m = 0; m < 4; m++) {
        size_t pix = (size_t)((b * Hn + h0 + m) * Wn + w);
        *(uint2*)(Y + pix * STRIDE + q * 4) = f_to_h4(acc[m].x, acc[m].y, acc[m].z, acc[m].w);
    }
}

// ---------------- kernel 3: SGEMM (f32x2), BK=16, + bias + mish, fp16 I/O ----------------
// BM=128, BK=16, 256 threads, microtile 8 x TN_ via 4 m-pairs of f32x2.
template<int BN_, int TN_, int KTILES>
__global__ __launch_bounds__(256)
void sgemm_mish(const __half* __restrict__ X, int ldX,
                const float* __restrict__ Wp,
                const float* __restrict__ bias,
                __half* __restrict__ Y)
{
    __shared__ float As[2][16][128];
    __shared__ float Bs[2][16][BN_];

    const int tid = threadIdx.x;
    const int px0 = blockIdx.x * 128;

    // A loader: 128 rows x 16 ch per tile, 8 ch/thread via one uint4 (8 halves)
    const int arow = tid >> 1;
    const int acol = (tid & 1) * 8;
    const __half* aptr = X + (size_t)(px0 + arow) * ldX + acol;

    // B loader: 16 rows x BN_ cols per tile
    const int brow = (BN_ == 128) ? (tid >> 5)      : (tid / (BN_ / 4));
    const int bcol = (BN_ == 128) ? ((tid & 31) * 4) : ((tid % (BN_ / 4)) * 4);
    const float* bptr = Wp + (size_t)brow * BN_ + bcol;
    const bool bload = (BN_ == 128) || (tid < 4 * BN_);

    const int tcx = tid & 15;
    const int tcy = tid >> 4;

    unsigned long long accp[4][TN_];
#pragma unroll
    for (int j = 0; j < 4; j++)
#pragma unroll
        for (int n = 0; n < TN_; n++) accp[j][n] = 0ULL;

    uint4 araw = *(const uint4*)aptr;
    float4 bv0, bv1;
    if (bload) {
        bv0 = *(const float4*)bptr;
        if (BN_ == 128) bv1 = *(const float4*)(bptr + 8 * BN_);
    }

    auto commit = [&](int buf, uint4 ar, float4 b0, float4 b1) {
        float af[8];
        h4_to_f(make_uint2(ar.x, ar.y), af);
        h4_to_f(make_uint2(ar.z, ar.w), af + 4);
#pragma unroll
        for (int j = 0; j < 8; j++) As[buf][acol + j][arow] = af[j];
        if (bload) {
            *(float4*)&Bs[buf][brow][bcol] = b0;
            if (BN_ == 128) *(float4*)&Bs[buf][brow + 8][bcol] = b1;
        }
    };

    commit(0, araw, bv0, bv1);
    __syncthreads();

#pragma unroll 1
    for (int kt = 0; kt < KTILES; kt++) {
        const int buf = kt & 1;
        if (kt + 1 < KTILES) {
            araw = *(const uint4*)(aptr + (kt + 1) * 16);
            if (bload) {
                bv0 = *(const float4*)(bptr + (size_t)(kt + 1) * 16 * BN_);
                if (BN_ == 128) bv1 = *(const float4*)(bptr + (size_t)(kt + 1) * 16 * BN_ + 8 * BN_);
            }
        }
#pragma unroll
        for (int kk = 0; kk < 16; kk++) {
            float4 a0 = *(const float4*)&As[buf][kk][tcy * 4];
            float4 a1 = *(const float4*)&As[buf][kk][tcy * 4 + 64];
            unsigned long long ap[4];
            ap[0] = pack2(a0.x, a0.y);
            ap[1] = pack2(a0.z, a0.w);
            ap[2] = pack2(a1.x, a1.y);
            ap[3] = pack2(a1.z, a1.w);

            float br[TN_];
            if constexpr (TN_ == 8) {
                float4 b0 = *(const float4*)&Bs[buf][kk][tcx * 4];
                float4 b1 = *(const float4*)&Bs[buf][kk][tcx * 4 + 64];
                br[0] = b0.x; br[1] = b0.y; br[2] = b0.z; br[3] = b0.w;
                br[4] = b1.x; br[5] = b1.y; br[6] = b1.z; br[7] = b1.w;
            } else if constexpr (TN_ == 4) {
                float4 b0 = *(const float4*)&Bs[buf][kk][tcx * 4];
                br[0] = b0.x; br[1] = b0.y; br[2] = b0.z; br[3] = b0.w;
            } else if constexpr (TN_ == 2) {
                float2 b0 = *(const float2*)&Bs[buf][kk][tcx * 2];
                br[0] = b0.x; br[1] = b0.y;
            } else {
                br[0] = Bs[buf][kk][tcx];
            }
            unsigned long long bd[TN_];
#pragma unroll
            for (int n = 0; n < TN_; n++) bd[n] = pack2(br[n], br[n]);
#pragma unroll
            for (int j = 0; j < 4; j++)
#pragma unroll
                for (int n = 0; n < TN_; n++)
                    ffma2(accp[j][n], ap[j], bd[n]);
        }
        if (kt + 1 < KTILES) {
            commit(buf ^ 1, araw, bv0, bv1);
        }
        __syncthreads();
    }

    float acc[8][TN_];
#pragma unroll
    for (int j = 0; j < 4; j++)
#pragma unroll
        for (int n = 0; n < TN_; n++)
            unpack2(accp[j][n], acc[2 * j][n], acc[2 * j + 1][n]);

    float bb[TN_];
    if constexpr (TN_ == 8) {
        float4 t0 = *(const float4*)&bias[tcx * 4];
        float4 t1 = *(const float4*)&bias[tcx * 4 + 64];
        bb[0]=t0.x; bb[1]=t0.y; bb[2]=t0.z; bb[3]=t0.w;
        bb[4]=t1.x; bb[5]=t1.y; bb[6]=t1.z; bb[7]=t1.w;
    } else if constexpr (TN_ == 4) {
        float4 t0 = *(const float4*)&bias[tcx * 4];
        bb[0]=t0.x; bb[1]=t0.y; bb[2]=t0.z; bb[3]=t0.w;
    } else if constexpr (TN_ == 2) {
        float2 t0 = *(const float2*)&bias[tcx * 2];
        bb[0]=t0.x; bb[1]=t0.y;
    } else {
        bb[0] = bias[tcx];
    }

#pragma unroll
    for (int g = 0; g < 2; g++) {
#pragma unroll
        for (int m = 0; m < 4; m++) {
            int px = px0 + tcy * 4 + m + g * 64;
            __half* yr = Y + (size_t)px * BN_;
            float ov[TN_];
#pragma unroll
            for (int n = 0; n < TN_; n++) ov[n] = mish(acc[g * 4 + m][n] + bb[n]);
            if constexpr (TN_ == 8) {
                *(uint2*)&yr[tcx * 4]      = f_to_h4(ov[0], ov[1], ov[2], ov[3]);
                *(uint2*)&yr[tcx * 4 + 64] = f_to_h4(ov[4], ov[5], ov[6], ov[7]);
            } else if constexpr (TN_ == 4) {
                *(uint2*)&yr[tcx * 4] = f_to_h4(ov[0], ov[1], ov[2], ov[3]);
            } else if constexpr (TN_ == 2) {
                __half2 h = __floats2half2_rn(ov[0], ov[1]);
                *(__half2*)&yr[tcx * 2] = h;
            } else {
                yr[tcx] = __float2half_rn(ov[0]);
            }
        }
    }
}

// ---------------- kernel 4: BN + 3x3 flow conv + scale (smem-tiled) ----------------
__global__ __launch_bounds__(256)
void final_kernel(const __half* __restrict__ X,
                  const float* __restrict__ gamma, const float* __restrict__ beta,
                  const float* __restrict__ mean,  const float* __restrict__ var,
                  const float* __restrict__ Wf, float* __restrict__ out)
{
    __shared__ float s[10 * 34 * 20];
    __shared__ float sw[9 * 32];

    const int tid = threadIdx.x;
    const int tx  = tid & 31;
    const int ty  = tid >> 5;
    const int bx = blockIdx.x, by = blockIdx.y, b = blockIdx.z;

    float sc[16], sh2[16];
#pragma unroll
    for (int c = 0; c < 16; c++) {
        float scale = gamma[c] * rsqrtf(var[c] + BN_EPS);
        sc[c] = scale;
        sh2[c] = beta[c] - mean[c] * scale;
    }
    for (int i = tid; i < 288; i += 256) sw[i] = Wf[i];

    for (int i = tid; i < 34 * 10 * 16; i += 256) {
        int c    = i & 15;
        int slot = i >> 4;
        int xs = slot % 34;
        int ys = slot / 34;
        int gx = bx * 32 + xs - 1;
        int gy = by * 8 + ys - 1;
        float v = 0.f;
        if (gx >= 0 && gx < Wn && gy >= 0 && gy < Hn) {
            float xr = __half2float(X[((size_t)((b * Hn + gy) * Wn + gx)) * 16 + c]);
            v = xr * sc[c] + sh2[c];
        }
        s[slot * 20 + c] = v;
    }
    __syncthreads();

    float f0 = 0.f, f1 = 0.f;
#pragma unroll
    for (int dy = 0; dy < 3; dy++) {
#pragma unroll
        for (int dx = 0; dx < 3; dx++) {
            const float* base = &s[((ty + dy) * 34 + (tx + dx)) * 20];
            const float* wr = &sw[(dy * 3 + dx) * 32];
#pragma unroll
            for (int g = 0; g < 4; g++) {
                float4 xv = *(const float4*)(base + g * 4);
                f0 = fmaf(xv.x, wr[(g * 4 + 0) * 2],     f0);
                f1 = fmaf(xv.x, wr[(g * 4 + 0) * 2 + 1], f1);
                f0 = fmaf(xv.y, wr[(g * 4 + 1) * 2],     f0);
                f1 = fmaf(xv.y, wr[(g * 4 + 1) * 2 + 1], f1);
                f0 = fmaf(xv.z, wr[(g * 4 + 2) * 2],     f0);
                f1 = fmaf(xv.z, wr[(g * 4 + 2) * 2 + 1], f1);
                f0 = fmaf(xv.w, wr[(g * 4 + 3) * 2],     f0);
                f1 = fmaf(xv.w, wr[(g * 4 + 3) * 2 + 1], f1);
            }
        }
    }

    size_t pix = (size_t)(b * Hn + by * 8 + ty) * Wn + bx * 32 + tx;
    out[pix * 2 + 0] = FLOW_SCALE * f0;
    out[pix * 2 + 1] = FLOW_SCALE * f1;
}

// ---------------- launch ----------------
extern "C" void kernel_launch(void* const* d_in, const int* in_sizes, int n_in,
                              void* d_out, int out_size)
{
    const float* prv   = (const float*)d_in[0];
    const float* nxt   = (const float*)d_in[1];
    const float* dw0   = (const float*)d_in[2];
    const float* pw0   = (const float*)d_in[3];
    const float* b0    = (const float*)d_in[4];
    const float* dw1   = (const float*)d_in[5];
    const float* pw1   = (const float*)d_in[6];
    const float* b1    = (const float*)d_in[7];
    const float* dw2   = (const float*)d_in[8];
    const float* pw2   = (const float*)d_in[9];
    const float* b2    = (const float*)d_in[10];
    const float* dw3   = (const float*)d_in[11];
    const float* pw3   = (const float*)d_in[12];
    const float* b3    = (const float*)d_in[13];
    const float* bng   = (const float*)d_in[14];
    const float* bnb   = (const float*)d_in[15];
    const float* bnm   = (const float*)d_in[16];
    const float* bnv   = (const float*)d_in[17];
    const float* flw   = (const float*)d_in[18];
    float* out = (float*)d_out;

    __half *A = nullptr, *Bb = nullptr;
    float *W0 = nullptr, *PW0 = nullptr;
    cudaGetSymbolAddress((void**)&A,   g_bufA);
    cudaGetSymbolAddress((void**)&Bb,  g_bufB);
    cudaGetSymbolAddress((void**)&W0,  g_dw0pad);
    cudaGetSymbolAddress((void**)&PW0, g_pw0pad);

    pad_w_kernel<<<(P0 * 128 + 255) / 256, 256>>>(dw0, pw0);

    // cost volume + concat -> A [NPIX, 224] fp16
    {
        dim3 grid(Wn / 32, Hn / 8, Bn);
        cost_kernel<0, 5><<<grid, 128>>>(prv, nxt, A);
        cost_kernel<5, 4><<<grid, 128>>>(prv, nxt, A);
    }

    // layer 0 (K padded to 224 = 14 * 16)
    dw4y_kernel<56, P0, P0><<<((NPIX / 4) * 56 + 255) / 256, 256>>>(A, W0, Bb);
    sgemm_mish<128, 8, 14><<<NPIX / 128, 256>>>(Bb, P0, PW0, b0, A);
    // layer 1
    dw4y_kernel<32, 128, 128><<<((NPIX / 4) * 32 + 255) / 256, 256>>>(A, dw1, Bb);
    sgemm_mish<64, 4, 8><<<NPIX / 128, 256>>>(Bb, 128, pw1, b1, A);
    // layer 2
    dw4y_kernel<16, 64, 64><<<((NPIX / 4) * 16 + 255) / 256, 256>>>(A, dw2, Bb);
    sgemm_mish<32, 2, 4><<<NPIX / 128, 256>>>(Bb, 64, pw2, b2, A);
    // layer 3
    dw4y_kernel<8, 32, 32><<<((NPIX / 4) * 8 + 255) / 256, 256>>>(A, dw3, Bb);
    sgemm_mish<16, 1, 2><<<NPIX / 128, 256>>>(Bb, 32, pw3, b3, A);

    // BN + flow conv + scale (tiled)
    {
        dim3 grid(Wn / 32, Hn / 8, Bn);
        final_kernel<<<grid, 256>>>(A, bng, bnb, bnm, bnv, flw, out);
    }
}